// round 4
// baseline (speedup 1.0000x reference)
#include <cuda_runtime.h>

#define NNODES 50000
#define DD 128
#define LN_EPS 1e-5f

// ---- scratch (device globals; no allocation allowed) ----
__device__ float g_agg[NNODES * DD];   // SpMM accumulator
__device__ float g_h1[NNODES * DD];    // layer-1 output
__device__ float g_iso[NNODES];        // rsqrt(out-degree)  (raw count first)
__device__ float g_isi[NNODES];        // rsqrt(in-degree)

// ---- zero agg + degree counters ----
__global__ void zero_deg_agg(int n) {
    int stride = gridDim.x * blockDim.x;
    int i = blockIdx.x * blockDim.x + threadIdx.x;
    int total4 = n * (DD / 4);
    float4 z = make_float4(0.f, 0.f, 0.f, 0.f);
    for (int idx = i; idx < total4; idx += stride)
        reinterpret_cast<float4*>(g_agg)[idx] = z;
    for (int idx = i; idx < n; idx += stride) {
        g_iso[idx] = 0.f;
        g_isi[idx] = 0.f;
    }
}

__global__ void zero_agg(int n) {
    int stride = gridDim.x * blockDim.x;
    int i = blockIdx.x * blockDim.x + threadIdx.x;
    int total4 = n * (DD / 4);
    float4 z = make_float4(0.f, 0.f, 0.f, 0.f);
    for (int idx = i; idx < total4; idx += stride)
        reinterpret_cast<float4*>(g_agg)[idx] = z;
}

// ---- degree accumulation (int32 indices!) ----
__global__ void deg_kernel(const int* __restrict__ src,
                           const int* __restrict__ dst, int e) {
    int i = blockIdx.x * blockDim.x + threadIdx.x;
    if (i < e) {
        atomicAdd(&g_iso[src[i]], 1.f);
        atomicAdd(&g_isi[dst[i]], 1.f);
    }
}

__global__ void deg_finalize(int n) {
    int i = blockIdx.x * blockDim.x + threadIdx.x;
    if (i < n) {
        g_iso[i] = rsqrtf(fmaxf(g_iso[i], 1.f));
        g_isi[i] = rsqrtf(fmaxf(g_isi[i], 1.f));
    }
}

// ---- SpMM: one warp per edge; gather src row (scaled by iso[src]),
//      atomicAdd into agg[dst].  h==nullptr means read from g_h1. ----
__global__ void scatter_kernel(const float* __restrict__ h,
                               const int* __restrict__ src,
                               const int* __restrict__ dst, int e) {
    const float* hp = h ? h : g_h1;
    int gw = (blockIdx.x * blockDim.x + threadIdx.x) >> 5;
    int lane = threadIdx.x & 31;
    if (gw >= e) return;
    int s = src[gw];
    int d = dst[gw];
    float sc = g_iso[s];
    float4 v = reinterpret_cast<const float4*>(hp + (size_t)s * DD)[lane];
    float* ap = g_agg + (size_t)d * DD + lane * 4;
    atomicAdd(ap + 0, v.x * sc);
    atomicAdd(ap + 1, v.y * sc);
    atomicAdd(ap + 2, v.z * sc);
    atomicAdd(ap + 3, v.w * sc);
}

// ---- fused (agg*isi) @ W + b -> LayerNorm -> ReLU ----
// Block: 256 threads (16x16), tile 64 rows x 128 cols, BK=16.
// out==nullptr means write to g_h1.
__global__ __launch_bounds__(256)
void gemm_ln_relu(const float* __restrict__ W,
                  const float* __restrict__ b,
                  const float* __restrict__ gamma,
                  const float* __restrict__ beta,
                  float* __restrict__ out, int n) {
    float* op = out ? out : g_h1;

    __shared__ float As[16][68];   // [k][row], padded
    __shared__ float Bs[16][128];  // [k][col]

    int tid = threadIdx.x;
    int tx = tid & 15;   // col group
    int ty = tid >> 4;   // row group
    int rowBase = blockIdx.x * 64;

    float acc[4][8];
#pragma unroll
    for (int i = 0; i < 4; i++)
#pragma unroll
        for (int j = 0; j < 8; j++) acc[i][j] = 0.f;

    int r = tid >> 2;      // 0..63
    int q = tid & 3;       // 0..3 (float4 within 16-wide k tile)
    int grow_ld = rowBase + r;
    float sc_ld = (grow_ld < n) ? g_isi[grow_ld] : 0.f;

    for (int k0 = 0; k0 < 128; k0 += 16) {
        // A tile: 64 rows x 16 k, scaled by isi[row]
        float4 av = make_float4(0.f, 0.f, 0.f, 0.f);
        if (grow_ld < n)
            av = *reinterpret_cast<const float4*>(
                g_agg + (size_t)grow_ld * DD + k0 + q * 4);
        As[q * 4 + 0][r] = av.x * sc_ld;
        As[q * 4 + 1][r] = av.y * sc_ld;
        As[q * 4 + 2][r] = av.z * sc_ld;
        As[q * 4 + 3][r] = av.w * sc_ld;

        // B tile: 16 k x 128 cols
#pragma unroll
        for (int u = 0; u < 2; u++) {
            int idx = tid + u * 256;
            int br = idx >> 5;
            int c4 = idx & 31;
            float4 bv = *reinterpret_cast<const float4*>(
                W + (size_t)(k0 + br) * DD + c4 * 4);
            *reinterpret_cast<float4*>(&Bs[br][c4 * 4]) = bv;
        }
        __syncthreads();

#pragma unroll
        for (int kk = 0; kk < 16; kk++) {
            float a0 = As[kk][ty * 4 + 0];
            float a1 = As[kk][ty * 4 + 1];
            float a2 = As[kk][ty * 4 + 2];
            float a3 = As[kk][ty * 4 + 3];
#pragma unroll
            for (int j = 0; j < 8; j++) {
                float bb = Bs[kk][tx + j * 16];
                acc[0][j] = fmaf(a0, bb, acc[0][j]);
                acc[1][j] = fmaf(a1, bb, acc[1][j]);
                acc[2][j] = fmaf(a2, bb, acc[2][j]);
                acc[3][j] = fmaf(a3, bb, acc[3][j]);
            }
        }
        __syncthreads();
    }

    // epilogue: +bias, LayerNorm over the 128-wide row, ReLU
#pragma unroll
    for (int i = 0; i < 4; i++) {
        int grow = rowBase + ty * 4 + i;
        float v[8];
        float s = 0.f, s2 = 0.f;
#pragma unroll
        for (int j = 0; j < 8; j++) {
            int col = tx + j * 16;
            v[j] = acc[i][j] + b[col];
            s += v[j];
            s2 += v[j] * v[j];
        }
        // reduce across the 16 lanes that share this row
#pragma unroll
        for (int m = 1; m < 16; m <<= 1) {
            s  += __shfl_xor_sync(0xffffffffu, s,  m);
            s2 += __shfl_xor_sync(0xffffffffu, s2, m);
        }
        float mu  = s * (1.f / 128.f);
        float var = s2 * (1.f / 128.f) - mu * mu;
        float inv = rsqrtf(var + LN_EPS);
        if (grow < n) {
#pragma unroll
            for (int j = 0; j < 8; j++) {
                int col = tx + j * 16;
                float y = (v[j] - mu) * inv * gamma[col] + beta[col];
                op[(size_t)grow * DD + col] = fmaxf(y, 0.f);
            }
        }
    }
}

extern "C" void kernel_launch(void* const* d_in, const int* in_sizes, int n_in,
                              void* d_out, int out_size) {
    const float* features = (const float*)d_in[0];
    const int*   src      = (const int*)d_in[1];
    const int*   dst      = (const int*)d_in[2];
    const float* W1  = (const float*)d_in[3];
    const float* b1  = (const float*)d_in[4];
    const float* g1  = (const float*)d_in[5];
    const float* be1 = (const float*)d_in[6];
    const float* W2  = (const float*)d_in[7];
    const float* b2  = (const float*)d_in[8];
    const float* g2  = (const float*)d_in[9];
    const float* be2 = (const float*)d_in[10];
    float* out = (float*)d_out;

    int n = in_sizes[0] / DD;   // 50000
    int e = in_sizes[1];        // 800000

    const int ZB = 2048;
    int degBlocks   = (e + 255) / 256;
    int nBlocks     = (n + 255) / 256;
    int scatBlocks  = (int)(((long long)e * 32 + 255) / 256);
    int gemmBlocks  = (n + 63) / 64;

    // degrees (iso/isi) + zero agg
    zero_deg_agg<<<ZB, 256>>>(n);
    deg_kernel<<<degBlocks, 256>>>(src, dst, e);
    deg_finalize<<<nBlocks, 256>>>(n);

    // layer 1  (scatter reads features; gemm writes g_h1 via nullptr)
    scatter_kernel<<<scatBlocks, 256>>>(features, src, dst, e);
    gemm_ln_relu<<<gemmBlocks, 256>>>(W1, b1, g1, be1, nullptr, n);

    // layer 2  (scatter reads g_h1 via nullptr; gemm writes d_out)
    zero_agg<<<ZB, 256>>>(n);
    scatter_kernel<<<scatBlocks, 256>>>(nullptr, src, dst, e);
    gemm_ln_relu<<<gemmBlocks, 256>>>(W2, b2, g2, be2, out, n);
}

// round 5
// speedup vs baseline: 2.7415x; 2.7415x over previous
#include <cuda_runtime.h>

#define NNODES 50000
#define EDGES  800000
#define DD 128
#define LN_EPS 1e-5f

// ---- scratch (device globals; no allocation allowed) ----
__device__ float g_agg[NNODES * DD];   // SpMM output
__device__ float g_h1[NNODES * DD];    // layer-1 output
__device__ float g_iso[NNODES];        // rsqrt(out-degree)
__device__ float g_isi[NNODES];        // rsqrt(in-degree)
__device__ int   g_din[NNODES];
__device__ int   g_dout[NNODES];
__device__ int   g_cnt[NNODES];
__device__ int   g_scan[NNODES];
__device__ int   g_bsum[64];
__device__ int   g_off[NNODES + 1];
__device__ int   g_csr_src[EDGES];     // src node of each in-edge, grouped by dst

// ---- zero int counters ----
__global__ void zero_counts(int n) {
    int i = blockIdx.x * blockDim.x + threadIdx.x;
    if (i < n) { g_din[i] = 0; g_dout[i] = 0; g_cnt[i] = 0; }
}

// ---- integer degree histogram ----
__global__ void deg_count(const int* __restrict__ src,
                          const int* __restrict__ dst, int e) {
    int i = blockIdx.x * blockDim.x + threadIdx.x;
    if (i < e) {
        atomicAdd(&g_dout[src[i]], 1);
        atomicAdd(&g_din[dst[i]], 1);
    }
}

// ---- prefix scan of g_din (3 kernels) ----
__global__ void scan_blocks(int n) {
    __shared__ int sh[1024];
    int gid = blockIdx.x * 1024 + threadIdx.x;
    int v = (gid < n) ? g_din[gid] : 0;
    sh[threadIdx.x] = v;
    __syncthreads();
#pragma unroll
    for (int off = 1; off < 1024; off <<= 1) {
        int t = (threadIdx.x >= off) ? sh[threadIdx.x - off] : 0;
        __syncthreads();
        sh[threadIdx.x] += t;
        __syncthreads();
    }
    if (gid < n) g_scan[gid] = sh[threadIdx.x];          // inclusive
    if (threadIdx.x == 1023) g_bsum[blockIdx.x] = sh[1023];
}

__global__ void scan_partials(int nb) {
    if (threadIdx.x == 0) {
        int run = 0;
        for (int i = 0; i < nb; i++) { int t = g_bsum[i]; g_bsum[i] = run; run += t; }
    }
}

__global__ void finalize_off(int n, int e) {
    int gid = blockIdx.x * blockDim.x + threadIdx.x;
    if (gid < n) {
        int incl = g_scan[gid] + g_bsum[gid >> 10];
        g_off[gid] = incl - g_din[gid];                  // exclusive
        g_iso[gid] = rsqrtf(fmaxf((float)g_dout[gid], 1.f));
        g_isi[gid] = rsqrtf(fmaxf((float)g_din[gid], 1.f));
    }
    if (gid == 0) g_off[n] = e;
}

// ---- fill CSR (by dst) ----
__global__ void fill_csr(const int* __restrict__ src,
                         const int* __restrict__ dst, int e) {
    int i = blockIdx.x * blockDim.x + threadIdx.x;
    if (i < e) {
        int d = dst[i];
        int pos = g_off[d] + atomicAdd(&g_cnt[d], 1);
        g_csr_src[pos] = src[i];
    }
}

// ---- pull-model SpMM: one warp per dst node, register accumulation.
//      h==nullptr means read from g_h1. Output pre-scaled by iso (src)
//      and isi (dst). ----
__global__ void gather_spmm(const float* __restrict__ h, int n) {
    const float* hp = h ? h : g_h1;
    int w = (blockIdx.x * blockDim.x + threadIdx.x) >> 5;
    int lane = threadIdx.x & 31;
    if (w >= n) return;
    int beg = g_off[w], end = g_off[w + 1];
    float4 acc = make_float4(0.f, 0.f, 0.f, 0.f);

    int i = beg;
    for (; i + 4 <= end; i += 4) {
        int s0 = g_csr_src[i + 0];
        int s1 = g_csr_src[i + 1];
        int s2 = g_csr_src[i + 2];
        int s3 = g_csr_src[i + 3];
        float c0 = g_iso[s0], c1 = g_iso[s1], c2 = g_iso[s2], c3 = g_iso[s3];
        float4 v0 = reinterpret_cast<const float4*>(hp + (size_t)s0 * DD)[lane];
        float4 v1 = reinterpret_cast<const float4*>(hp + (size_t)s1 * DD)[lane];
        float4 v2 = reinterpret_cast<const float4*>(hp + (size_t)s2 * DD)[lane];
        float4 v3 = reinterpret_cast<const float4*>(hp + (size_t)s3 * DD)[lane];
        acc.x = fmaf(c0, v0.x, fmaf(c1, v1.x, fmaf(c2, v2.x, fmaf(c3, v3.x, acc.x))));
        acc.y = fmaf(c0, v0.y, fmaf(c1, v1.y, fmaf(c2, v2.y, fmaf(c3, v3.y, acc.y))));
        acc.z = fmaf(c0, v0.z, fmaf(c1, v1.z, fmaf(c2, v2.z, fmaf(c3, v3.z, acc.z))));
        acc.w = fmaf(c0, v0.w, fmaf(c1, v1.w, fmaf(c2, v2.w, fmaf(c3, v3.w, acc.w))));
    }
    for (; i < end; i++) {
        int s = g_csr_src[i];
        float c = g_iso[s];
        float4 v = reinterpret_cast<const float4*>(hp + (size_t)s * DD)[lane];
        acc.x = fmaf(c, v.x, acc.x);
        acc.y = fmaf(c, v.y, acc.y);
        acc.z = fmaf(c, v.z, acc.z);
        acc.w = fmaf(c, v.w, acc.w);
    }
    float si = g_isi[w];
    acc.x *= si; acc.y *= si; acc.z *= si; acc.w *= si;
    reinterpret_cast<float4*>(g_agg + (size_t)w * DD)[lane] = acc;
}

// ---- fused agg @ W + b -> LayerNorm -> ReLU ----
// Block: 256 threads (16x16), tile 64 rows x 128 cols, BK=16.
// out==nullptr means write to g_h1.
__global__ __launch_bounds__(256)
void gemm_ln_relu(const float* __restrict__ W,
                  const float* __restrict__ b,
                  const float* __restrict__ gamma,
                  const float* __restrict__ beta,
                  float* __restrict__ out, int n) {
    float* op = out ? out : g_h1;

    __shared__ float As[16][68];   // [k][row], padded
    __shared__ float Bs[16][128];  // [k][col]

    int tid = threadIdx.x;
    int tx = tid & 15;   // col group
    int ty = tid >> 4;   // row group
    int rowBase = blockIdx.x * 64;

    float acc[4][8];
#pragma unroll
    for (int i = 0; i < 4; i++)
#pragma unroll
        for (int j = 0; j < 8; j++) acc[i][j] = 0.f;

    int r = tid >> 2;      // 0..63
    int q = tid & 3;       // 0..3
    int grow_ld = rowBase + r;

    for (int k0 = 0; k0 < 128; k0 += 16) {
        float4 av = make_float4(0.f, 0.f, 0.f, 0.f);
        if (grow_ld < n)
            av = *reinterpret_cast<const float4*>(
                g_agg + (size_t)grow_ld * DD + k0 + q * 4);
        As[q * 4 + 0][r] = av.x;
        As[q * 4 + 1][r] = av.y;
        As[q * 4 + 2][r] = av.z;
        As[q * 4 + 3][r] = av.w;

#pragma unroll
        for (int u = 0; u < 2; u++) {
            int idx = tid + u * 256;
            int br = idx >> 5;
            int c4 = idx & 31;
            float4 bv = *reinterpret_cast<const float4*>(
                W + (size_t)(k0 + br) * DD + c4 * 4);
            *reinterpret_cast<float4*>(&Bs[br][c4 * 4]) = bv;
        }
        __syncthreads();

#pragma unroll
        for (int kk = 0; kk < 16; kk++) {
            float a0 = As[kk][ty * 4 + 0];
            float a1 = As[kk][ty * 4 + 1];
            float a2 = As[kk][ty * 4 + 2];
            float a3 = As[kk][ty * 4 + 3];
#pragma unroll
            for (int j = 0; j < 8; j++) {
                float bb = Bs[kk][tx + j * 16];
                acc[0][j] = fmaf(a0, bb, acc[0][j]);
                acc[1][j] = fmaf(a1, bb, acc[1][j]);
                acc[2][j] = fmaf(a2, bb, acc[2][j]);
                acc[3][j] = fmaf(a3, bb, acc[3][j]);
            }
        }
        __syncthreads();
    }

#pragma unroll
    for (int i = 0; i < 4; i++) {
        int grow = rowBase + ty * 4 + i;
        float v[8];
        float s = 0.f, s2 = 0.f;
#pragma unroll
        for (int j = 0; j < 8; j++) {
            int col = tx + j * 16;
            v[j] = acc[i][j] + b[col];
            s += v[j];
            s2 += v[j] * v[j];
        }
#pragma unroll
        for (int m = 1; m < 16; m <<= 1) {
            s  += __shfl_xor_sync(0xffffffffu, s,  m);
            s2 += __shfl_xor_sync(0xffffffffu, s2, m);
        }
        float mu  = s * (1.f / 128.f);
        float var = s2 * (1.f / 128.f) - mu * mu;
        float inv = rsqrtf(var + LN_EPS);
        if (grow < n) {
#pragma unroll
            for (int j = 0; j < 8; j++) {
                int col = tx + j * 16;
                float y = (v[j] - mu) * inv * gamma[col] + beta[col];
                op[(size_t)grow * DD + col] = fmaxf(y, 0.f);
            }
        }
    }
}

extern "C" void kernel_launch(void* const* d_in, const int* in_sizes, int n_in,
                              void* d_out, int out_size) {
    const float* features = (const float*)d_in[0];
    const int*   src      = (const int*)d_in[1];
    const int*   dst      = (const int*)d_in[2];
    const float* W1  = (const float*)d_in[3];
    const float* b1  = (const float*)d_in[4];
    const float* g1  = (const float*)d_in[5];
    const float* be1 = (const float*)d_in[6];
    const float* W2  = (const float*)d_in[7];
    const float* b2  = (const float*)d_in[8];
    const float* g2  = (const float*)d_in[9];
    const float* be2 = (const float*)d_in[10];
    float* out = (float*)d_out;

    int n = in_sizes[0] / DD;   // 50000
    int e = in_sizes[1];        // 800000

    int nBlocks    = (n + 255) / 256;
    int eBlocks    = (e + 255) / 256;
    int scanBlocks = (n + 1023) / 1024;
    int gathBlocks = (int)(((long long)n * 32 + 255) / 256);
    int gemmBlocks = (n + 63) / 64;

    // ---- CSR build (once, reused by both layers) ----
    zero_counts<<<nBlocks, 256>>>(n);
    deg_count<<<eBlocks, 256>>>(src, dst, e);
    scan_blocks<<<scanBlocks, 1024>>>(n);
    scan_partials<<<1, 32>>>(scanBlocks);
    finalize_off<<<nBlocks, 256>>>(n, e);
    fill_csr<<<eBlocks, 256>>>(src, dst, e);

    // ---- layer 1 ----
    gather_spmm<<<gathBlocks, 256>>>(features, n);
    gemm_ln_relu<<<gemmBlocks, 256>>>(W1, b1, g1, be1, nullptr, n);

    // ---- layer 2 ----
    gather_spmm<<<gathBlocks, 256>>>(nullptr, n);
    gemm_ln_relu<<<gemmBlocks, 256>>>(W2, b2, g2, be2, out, n);
}

// round 6
// speedup vs baseline: 2.7502x; 1.0032x over previous
#include <cuda_runtime.h>

#define NNODES 50000
#define EDGES  800000
#define DD 128
#define LN_EPS 1e-5f

// ---- scratch (device globals; no allocation allowed) ----
__device__ float g_agg[NNODES * DD];   // SpMM output
__device__ float g_h1[NNODES * DD];    // layer-1 output
__device__ float g_iso[NNODES];        // rsqrt(out-degree)
__device__ float g_isi[NNODES];        // rsqrt(in-degree)
__device__ int   g_din[NNODES];
__device__ int   g_dout[NNODES];
__device__ int   g_cnt[NNODES];
__device__ int   g_scan[NNODES];
__device__ int   g_bsum[64];
__device__ int   g_off[NNODES + 1];
__device__ int   g_csr_src[EDGES];     // src node of each in-edge, grouped by dst

// ---- zero int counters ----
__global__ void zero_counts(int n) {
    int i = blockIdx.x * blockDim.x + threadIdx.x;
    if (i < n) { g_din[i] = 0; g_dout[i] = 0; g_cnt[i] = 0; }
}

// ---- integer degree histogram ----
__global__ void deg_count(const int* __restrict__ src,
                          const int* __restrict__ dst, int e) {
    int i = blockIdx.x * blockDim.x + threadIdx.x;
    if (i < e) {
        atomicAdd(&g_dout[src[i]], 1);
        atomicAdd(&g_din[dst[i]], 1);
    }
}

// ---- prefix scan of g_din (3 kernels) ----
__global__ void scan_blocks(int n) {
    __shared__ int sh[1024];
    int gid = blockIdx.x * 1024 + threadIdx.x;
    int v = (gid < n) ? g_din[gid] : 0;
    sh[threadIdx.x] = v;
    __syncthreads();
#pragma unroll
    for (int off = 1; off < 1024; off <<= 1) {
        int t = (threadIdx.x >= off) ? sh[threadIdx.x - off] : 0;
        __syncthreads();
        sh[threadIdx.x] += t;
        __syncthreads();
    }
    if (gid < n) g_scan[gid] = sh[threadIdx.x];          // inclusive
    if (threadIdx.x == 1023) g_bsum[blockIdx.x] = sh[1023];
}

__global__ void scan_partials(int nb) {
    if (threadIdx.x == 0) {
        int run = 0;
        for (int i = 0; i < nb; i++) { int t = g_bsum[i]; g_bsum[i] = run; run += t; }
    }
}

__global__ void finalize_off(int n, int e) {
    int gid = blockIdx.x * blockDim.x + threadIdx.x;
    if (gid < n) {
        int incl = g_scan[gid] + g_bsum[gid >> 10];
        g_off[gid] = incl - g_din[gid];                  // exclusive
        g_iso[gid] = rsqrtf(fmaxf((float)g_dout[gid], 1.f));
        g_isi[gid] = rsqrtf(fmaxf((float)g_din[gid], 1.f));
    }
    if (gid == 0) g_off[n] = e;
}

// ---- fill CSR (by dst) ----
__global__ void fill_csr(const int* __restrict__ src,
                         const int* __restrict__ dst, int e) {
    int i = blockIdx.x * blockDim.x + threadIdx.x;
    if (i < e) {
        int d = dst[i];
        int pos = g_off[d] + atomicAdd(&g_cnt[d], 1);
        g_csr_src[pos] = src[i];
    }
}

// ---- pull-model SpMM: one warp per dst node, register accumulation.
//      h==nullptr means read from g_h1. Output pre-scaled by iso (src)
//      and isi (dst). ----
__global__ void gather_spmm(const float* __restrict__ h, int n) {
    const float* hp = h ? h : g_h1;
    int w = (blockIdx.x * blockDim.x + threadIdx.x) >> 5;
    int lane = threadIdx.x & 31;
    if (w >= n) return;
    int beg = g_off[w], end = g_off[w + 1];
    float4 acc = make_float4(0.f, 0.f, 0.f, 0.f);

    int i = beg;
    for (; i + 4 <= end; i += 4) {
        int s0 = g_csr_src[i + 0];
        int s1 = g_csr_src[i + 1];
        int s2 = g_csr_src[i + 2];
        int s3 = g_csr_src[i + 3];
        float c0 = g_iso[s0], c1 = g_iso[s1], c2 = g_iso[s2], c3 = g_iso[s3];
        float4 v0 = reinterpret_cast<const float4*>(hp + (size_t)s0 * DD)[lane];
        float4 v1 = reinterpret_cast<const float4*>(hp + (size_t)s1 * DD)[lane];
        float4 v2 = reinterpret_cast<const float4*>(hp + (size_t)s2 * DD)[lane];
        float4 v3 = reinterpret_cast<const float4*>(hp + (size_t)s3 * DD)[lane];
        acc.x = fmaf(c0, v0.x, fmaf(c1, v1.x, fmaf(c2, v2.x, fmaf(c3, v3.x, acc.x))));
        acc.y = fmaf(c0, v0.y, fmaf(c1, v1.y, fmaf(c2, v2.y, fmaf(c3, v3.y, acc.y))));
        acc.z = fmaf(c0, v0.z, fmaf(c1, v1.z, fmaf(c2, v2.z, fmaf(c3, v3.z, acc.z))));
        acc.w = fmaf(c0, v0.w, fmaf(c1, v1.w, fmaf(c2, v2.w, fmaf(c3, v3.w, acc.w))));
    }
    for (; i < end; i++) {
        int s = g_csr_src[i];
        float c = g_iso[s];
        float4 v = reinterpret_cast<const float4*>(hp + (size_t)s * DD)[lane];
        acc.x = fmaf(c, v.x, acc.x);
        acc.y = fmaf(c, v.y, acc.y);
        acc.z = fmaf(c, v.z, acc.z);
        acc.w = fmaf(c, v.w, acc.w);
    }
    float si = g_isi[w];
    acc.x *= si; acc.y *= si; acc.z *= si; acc.w *= si;
    reinterpret_cast<float4*>(g_agg + (size_t)w * DD)[lane] = acc;
}

// ---- fused agg @ W + b -> LayerNorm -> ReLU ----
// Block: 256 threads (16x16), tile 64 rows x 128 cols, BK=16.
// out==nullptr means write to g_h1.
__global__ __launch_bounds__(256)
void gemm_ln_relu(const float* __restrict__ W,
                  const float* __restrict__ b,
                  const float* __restrict__ gamma,
                  const float* __restrict__ beta,
                  float* __restrict__ out, int n) {
    float* op = out ? out : g_h1;

    __shared__ float As[16][68];   // [k][row], padded
    __shared__ float Bs[16][128];  // [k][col]

    int tid = threadIdx.x;
    int tx = tid & 15;   // col group
    int ty = tid >> 4;   // row group
    int rowBase = blockIdx.x * 64;

    float acc[4][8];
#pragma unroll
    for (int i = 0; i < 4; i++)
#pragma unroll
        for (int j = 0; j < 8; j++) acc[i][j] = 0.f;

    int r = tid >> 2;      // 0..63
    int q = tid & 3;       // 0..3
    int grow_ld = rowBase + r;

    for (int k0 = 0; k0 < 128; k0 += 16) {
        float4 av = make_float4(0.f, 0.f, 0.f, 0.f);
        if (grow_ld < n)
            av = *reinterpret_cast<const float4*>(
                g_agg + (size_t)grow_ld * DD + k0 + q * 4);
        As[q * 4 + 0][r] = av.x;
        As[q * 4 + 1][r] = av.y;
        As[q * 4 + 2][r] = av.z;
        As[q * 4 + 3][r] = av.w;

#pragma unroll
        for (int u = 0; u < 2; u++) {
            int idx = tid + u * 256;
            int br = idx >> 5;
            int c4 = idx & 31;
            float4 bv = *reinterpret_cast<const float4*>(
                W + (size_t)(k0 + br) * DD + c4 * 4);
            *reinterpret_cast<float4*>(&Bs[br][c4 * 4]) = bv;
        }
        __syncthreads();

#pragma unroll
        for (int kk = 0; kk < 16; kk++) {
            float a0 = As[kk][ty * 4 + 0];
            float a1 = As[kk][ty * 4 + 1];
            float a2 = As[kk][ty * 4 + 2];
            float a3 = As[kk][ty * 4 + 3];
#pragma unroll
            for (int j = 0; j < 8; j++) {
                float bb = Bs[kk][tx + j * 16];
                acc[0][j] = fmaf(a0, bb, acc[0][j]);
                acc[1][j] = fmaf(a1, bb, acc[1][j]);
                acc[2][j] = fmaf(a2, bb, acc[2][j]);
                acc[3][j] = fmaf(a3, bb, acc[3][j]);
            }
        }
        __syncthreads();
    }

#pragma unroll
    for (int i = 0; i < 4; i++) {
        int grow = rowBase + ty * 4 + i;
        float v[8];
        float s = 0.f, s2 = 0.f;
#pragma unroll
        for (int j = 0; j < 8; j++) {
            int col = tx + j * 16;
            v[j] = acc[i][j] + b[col];
            s += v[j];
            s2 += v[j] * v[j];
        }
#pragma unroll
        for (int m = 1; m < 16; m <<= 1) {
            s  += __shfl_xor_sync(0xffffffffu, s,  m);
            s2 += __shfl_xor_sync(0xffffffffu, s2, m);
        }
        float mu  = s * (1.f / 128.f);
        float var = s2 * (1.f / 128.f) - mu * mu;
        float inv = rsqrtf(var + LN_EPS);
        if (grow < n) {
#pragma unroll
            for (int j = 0; j < 8; j++) {
                int col = tx + j * 16;
                float y = (v[j] - mu) * inv * gamma[col] + beta[col];
                op[(size_t)grow * DD + col] = fmaxf(y, 0.f);
            }
        }
    }
}

extern "C" void kernel_launch(void* const* d_in, const int* in_sizes, int n_in,
                              void* d_out, int out_size) {
    const float* features = (const float*)d_in[0];
    const int*   src      = (const int*)d_in[1];
    const int*   dst      = (const int*)d_in[2];
    const float* W1  = (const float*)d_in[3];
    const float* b1  = (const float*)d_in[4];
    const float* g1  = (const float*)d_in[5];
    const float* be1 = (const float*)d_in[6];
    const float* W2  = (const float*)d_in[7];
    const float* b2  = (const float*)d_in[8];
    const float* g2  = (const float*)d_in[9];
    const float* be2 = (const float*)d_in[10];
    float* out = (float*)d_out;

    int n = in_sizes[0] / DD;   // 50000
    int e = in_sizes[1];        // 800000

    int nBlocks    = (n + 255) / 256;
    int eBlocks    = (e + 255) / 256;
    int scanBlocks = (n + 1023) / 1024;
    int gathBlocks = (int)(((long long)n * 32 + 255) / 256);
    int gemmBlocks = (n + 63) / 64;

    // ---- CSR build (once, reused by both layers) ----
    zero_counts<<<nBlocks, 256>>>(n);
    deg_count<<<eBlocks, 256>>>(src, dst, e);
    scan_blocks<<<scanBlocks, 1024>>>(n);
    scan_partials<<<1, 32>>>(scanBlocks);
    finalize_off<<<nBlocks, 256>>>(n, e);
    fill_csr<<<eBlocks, 256>>>(src, dst, e);

    // ---- layer 1 ----
    gather_spmm<<<gathBlocks, 256>>>(features, n);
    gemm_ln_relu<<<gemmBlocks, 256>>>(W1, b1, g1, be1, nullptr, n);

    // ---- layer 2 ----
    gather_spmm<<<gathBlocks, 256>>>(nullptr, n);
    gemm_ln_relu<<<gemmBlocks, 256>>>(W2, b2, g2, be2, out, n);
}